// round 14
// baseline (speedup 1.0000x reference)
#include <cuda_runtime.h>
#include <cuda_fp16.h>
#include <math.h>

// x: (B=4, S=128, H=128, W=128) fp32 ; ada_mask: (B, S, K=21) fp32
// out[b,s,h,w] = sum_k softmax(ada_mask[b,s,:])[k] * xpad[b, s+k-10, h, w]
// Math in half2 (2 pixels/lane, HFMA2), I/O in fp32. ~3.5e-4 rel err (gate 1e-3).
#define B_DIM    4
#define S_DIM    128
#define HW2_DIM  8192                  // H*W / 2 (pixel pairs per plane)
#define K_DIM    21
#define PAD      10
#define TILE_S   16                    // output rows (s) per thread
#define THREADS  128
#define WROW     24                    // half2 weights per row: w0..w20 + 3 pad (uint4 align)
#define WIN      (TILE_S + K_DIM - 1)  // 36 planes, loaded upfront (proven best)

__global__ __launch_bounds__(THREADS, 6)
void AdaptiveMixing_28784870818046_kernel(const float2* __restrict__ x,
                                          const float*  __restrict__ ada_mask,
                                          float2* __restrict__ out)
{
    // duplicated weights: ws[j*WROW + k] = half2(w_k, w_k) for row s0+j
    __shared__ __align__(16) __half2 ws[TILE_S * WROW];

    const int b  = blockIdx.z;
    const int s0 = blockIdx.y * TILE_S;
    const int p  = blockIdx.x * THREADS + threadIdx.x;   // pixel-pair idx [0, HW2)

    // ---- per-(b,s) softmax over K=21 (fp32), stored as duplicated half2 ----
    if (threadIdx.x < TILE_S) {
        const int s = s0 + threadIdx.x;
        const float* m = ada_mask + ((size_t)b * S_DIM + s) * K_DIM;
        float mv[K_DIM];
        float mx = -3.402823466e+38f;
        #pragma unroll
        for (int k = 0; k < K_DIM; ++k) { mv[k] = m[k]; mx = fmaxf(mx, mv[k]); }
        float sum = 0.f;
        #pragma unroll
        for (int k = 0; k < K_DIM; ++k) { mv[k] = expf(mv[k] - mx); sum += mv[k]; }
        const float inv = 1.0f / sum;
        __half2* row = ws + threadIdx.x * WROW;
        #pragma unroll
        for (int k = 0; k < K_DIM; ++k)
            row[k] = __half2half2(__float2half_rn(mv[k] * inv));
        row[21] = __half2half2(__float2half_rn(0.f));
        row[22] = row[21];
        row[23] = row[21];
    }
    __syncthreads();

    // ---- upfront batched window: 36 planes, fp32 load -> half2 convert ----
    __half2 win[WIN];
    const float2* xb = x + (size_t)b * S_DIM * HW2_DIM + p;
    #pragma unroll
    for (int i = 0; i < WIN; ++i) {
        const int s = s0 - PAD + i;
        if (s >= 0 && s < S_DIM) {
            const float2 v = xb[(size_t)s * HW2_DIM];
            win[i] = __floats2half2_rn(v.x, v.y);
        } else {
            win[i] = __half2half2(__float2half_rn(0.f));
        }
    }

    // ---- 16 compute rows: 21 HFMA2 on a pixel pair, 3 accumulation chains ----
    float2* ob = out + ((size_t)b * S_DIM + s0) * HW2_DIM + p;
    #pragma unroll
    for (int j = 0; j < TILE_S; ++j) {
        const uint4* wr = reinterpret_cast<const uint4*>(ws + j * WROW);
        const __half2 z = __half2half2(__float2half_rn(0.f));
        __half2 A = z, B = z, C = z;
        #pragma unroll
        for (int q = 0; q < 5; ++q) {                    // k = 0..19 via LDS.128
            const uint4 w4 = wr[q];
            const __half2 w0 = *reinterpret_cast<const __half2*>(&w4.x);
            const __half2 w1 = *reinterpret_cast<const __half2*>(&w4.y);
            const __half2 w2 = *reinterpret_cast<const __half2*>(&w4.z);
            const __half2 w3 = *reinterpret_cast<const __half2*>(&w4.w);
            A = __hfma2(w0, win[j + 4*q + 0], A);
            B = __hfma2(w1, win[j + 4*q + 1], B);
            C = __hfma2(w2, win[j + 4*q + 2], C);
            A = __hfma2(w3, win[j + 4*q + 3], A);
        }
        B = __hfma2(ws[j * WROW + 20], win[j + 20], B);  // k = 20 singleton
        const __half2 s2 = __hadd2(__hadd2(A, C), B);
        const float2 r = __half22float2(s2);
        ob[(size_t)j * HW2_DIM] = r;
    }
}

extern "C" void kernel_launch(void* const* d_in, const int* in_sizes, int n_in,
                              void* d_out, int out_size)
{
    const float2* x       = (const float2*)d_in[0];   // (4,128,128,128) fp32 as pairs
    const float* ada_mask = (const float*)d_in[1];    // (4,128,21) fp32
    float2* out           = (float2*)d_out;

    dim3 grid(HW2_DIM / THREADS,   // 64 pixel-blocks
              S_DIM / TILE_S,      // 8 s-tiles
              B_DIM);              // 4 batches  => 2048 CTAs
    AdaptiveMixing_28784870818046_kernel<<<grid, THREADS>>>(x, ada_mask, out);
}

// round 15
// speedup vs baseline: 1.0115x; 1.0115x over previous
#include <cuda_runtime.h>
#include <math.h>

// x: (B=4, S=128, H=128, W=128) fp32 ; ada_mask: (B, S, K=21) fp32
// out[b,s,h,w] = sum_k softmax(ada_mask[b,s,:])[k] * xpad[b, s+k-10, h, w]
#define B_DIM    4
#define S_DIM    128
#define HW2_DIM  8192                  // H*W / 2 (float2 pixels per plane)
#define K_DIM    21
#define PAD      10
#define TILE_S   16                    // output rows (s) per thread
#define THREADS  128
#define WROW     22                    // weight row: 21 weights + 1 pad float
#define WIN      (TILE_S + K_DIM - 1)  // 36 planes per tile
#define BATCH1   21                    // front LDG batch (min for row 0) -> low MLP_p1

__global__ __launch_bounds__(THREADS, 5)
void AdaptiveMixing_28784870818046_kernel(const float2* __restrict__ x,
                                          const float*  __restrict__ ada_mask,
                                          float2* __restrict__ out)
{
    __shared__ __align__(16) float ws[TILE_S * WROW + 2];  // +2: float4 reads in-bounds

    const int b  = blockIdx.z;
    const int s0 = blockIdx.y * TILE_S;
    const int p  = blockIdx.x * THREADS + threadIdx.x;   // float2-pixel idx [0, HW2)

    const float2* xb = x + (size_t)b * S_DIM * HW2_DIM + p;

    // ---- batch 1: planes 0..20 (all of row 0's window) — 21-deep LDG burst.
    //      Kept to the feasible minimum to limit cross-CTA L1tex queue depth. ----
    float2 win[WIN];
    #pragma unroll
    for (int i = 0; i < BATCH1; ++i) {
        const int s = s0 - PAD + i;
        win[i] = (s >= 0 && s < S_DIM) ? xb[(size_t)s * HW2_DIM]
                                       : make_float2(0.f, 0.f);
    }

    // ---- softmax overlaps batch-1 latency ----
    if (threadIdx.x < TILE_S) {
        const int s = s0 + threadIdx.x;
        const float* m = ada_mask + ((size_t)b * S_DIM + s) * K_DIM;
        float mv[K_DIM];
        float mx = -3.402823466e+38f;
        #pragma unroll
        for (int k = 0; k < K_DIM; ++k) { mv[k] = m[k]; mx = fmaxf(mx, mv[k]); }
        float sum = 0.f;
        #pragma unroll
        for (int k = 0; k < K_DIM; ++k) { mv[k] = expf(mv[k] - mx); sum += mv[k]; }
        const float inv = 1.0f / sum;
        float* row = ws + threadIdx.x * WROW;
        #pragma unroll
        for (int k = 0; k < K_DIM; ++k) row[k] = mv[k] * inv;
        row[21] = 0.f;
    }
    __syncthreads();

    // ---- batch 2: planes 21..35 (s = s0+11..s0+25, only top clip), issued after
    //      the barrier; plane 21 is first consumed as the LAST fma of row 1,
    //      so these 15 loads overlap row-0/1 compute ----
    #pragma unroll
    for (int i = BATCH1; i < WIN; ++i) {
        const int s = s0 - PAD + i;
        win[i] = (s < S_DIM) ? xb[(size_t)s * HW2_DIM] : make_float2(0.f, 0.f);
    }

    // ---- 16 compute rows: 21-wide fp32 dot on a float2 pixel pair ----
    float2* ob = out + ((size_t)b * S_DIM + s0) * HW2_DIM + p;
    #pragma unroll
    for (int j = 0; j < TILE_S; ++j) {
        const float* row = ws + j * WROW;
        float a0x = 0.f, a0y = 0.f, a1x = 0.f, a1y = 0.f;  // 2 chains x 2 pixels
        #pragma unroll
        for (int q = 0; q < 5; ++q) {                      // k = 0..19 via float4 LDS
            const float4 w4 = reinterpret_cast<const float4*>(row)[q];
            const float2 v0 = win[j + 4*q + 0];
            const float2 v1 = win[j + 4*q + 1];
            const float2 v2 = win[j + 4*q + 2];
            const float2 v3 = win[j + 4*q + 3];
            a0x = fmaf(w4.x, v0.x, a0x);  a0y = fmaf(w4.x, v0.y, a0y);
            a1x = fmaf(w4.y, v1.x, a1x);  a1y = fmaf(w4.y, v1.y, a1y);
            a0x = fmaf(w4.z, v2.x, a0x);  a0y = fmaf(w4.z, v2.y, a0y);
            a1x = fmaf(w4.w, v3.x, a1x);  a1y = fmaf(w4.w, v3.y, a1y);
        }
        {                                                  // k = 20 singleton (last)
            const float w20 = row[20];
            const float2 v = win[j + 20];
            a0x = fmaf(w20, v.x, a0x);    a0y = fmaf(w20, v.y, a0y);
        }
        float2 r;
        r.x = a0x + a1x;
        r.y = a0y + a1y;
        ob[(size_t)j * HW2_DIM] = r;
    }
}

extern "C" void kernel_launch(void* const* d_in, const int* in_sizes, int n_in,
                              void* d_out, int out_size)
{
    const float2* x       = (const float2*)d_in[0];   // (4,128,128,128) fp32 as float2
    const float* ada_mask = (const float*)d_in[1];    // (4,128,21) fp32
    float2* out           = (float2*)d_out;

    dim3 grid(HW2_DIM / THREADS,   // 64 pixel-blocks
              S_DIM / TILE_S,      // 8 s-tiles
              B_DIM);              // 4 batches  => 2048 CTAs
    AdaptiveMixing_28784870818046_kernel<<<grid, THREADS>>>(x, ada_mask, out);
}